// round 5
// baseline (speedup 1.0000x reference)
#include <cuda_runtime.h>
#include <cuda_bf16.h>
#include <cstdint>

#define N_ROWS 65536
#define DIM    512
#define KC     256
#define BM     64        // rows per CTA
#define NCHK   4         // 4 col-chunks of 64
#define NTHR   256

// smem byte offsets (dynamic smem)
#define OFF_A    0                 // 64 x 512 bf16 = 65536
#define OFF_B0   65536             // 64 x 512 bf16 = 65536
#define OFF_B1   131072
#define OFF_SC   196608            // 64 x 65 f32 = 16640
#define OFF_CN   213248            // 256 f32
#define OFF_IDX  214272            // 64 int
#define SMEM_TOTAL 214528

__device__ __nv_bfloat16 g_Bbf[KC][DIM];   // centroids, bf16, [k][d]
__device__ float g_cnorm[KC];

__device__ __forceinline__ uint32_t smem_u32(const void* p) {
    uint32_t a;
    asm("{ .reg .u64 t; cvta.to.shared.u64 t, %1; cvt.u32.u64 %0, t; }" : "=r"(a) : "l"(p));
    return a;
}
__device__ __forceinline__ void cp16(uint32_t s, const void* g) {
    asm volatile("cp.async.cg.shared.global [%0], [%1], 16;" :: "r"(s), "l"(g) : "memory");
}
__device__ __forceinline__ void ldsm4(uint32_t& r0, uint32_t& r1, uint32_t& r2, uint32_t& r3, uint32_t a) {
    asm volatile("ldmatrix.sync.aligned.m8n8.x4.shared.b16 {%0,%1,%2,%3}, [%4];"
                 : "=r"(r0), "=r"(r1), "=r"(r2), "=r"(r3) : "r"(a));
}
__device__ __forceinline__ void mma16816(float* d, const uint32_t* a, const uint32_t* b) {
    asm volatile("mma.sync.aligned.m16n8k16.row.col.f32.bf16.bf16.f32 "
                 "{%0,%1,%2,%3}, {%4,%5,%6,%7}, {%8,%9}, {%0,%1,%2,%3};"
                 : "+f"(d[0]), "+f"(d[1]), "+f"(d[2]), "+f"(d[3])
                 : "r"(a[0]), "r"(a[1]), "r"(a[2]), "r"(a[3]), "r"(b[0]), "r"(b[1]));
}
__device__ __forceinline__ uint32_t b2u(__nv_bfloat162 v) {
    return ((uint32_t)__bfloat16_as_ushort(v.y) << 16) | __bfloat16_as_ushort(v.x);
}
__device__ __forceinline__ bool ltp(float a, int ia, float b, int ib) {
    return a < b || (a == b && ia < ib);
}

// ---------------------------------------------------------------------------
__global__ void prep_kernel(const float* __restrict__ C) {
    __shared__ double red[4];
    const int k = blockIdx.x, t = threadIdx.x;   // 128 thr
    double s = 0.0;
    for (int d = t; d < DIM; d += 128) {
        float v = C[(size_t)k * DIM + d];
        s += (double)v * (double)v;
        g_Bbf[k][d] = __float2bfloat16_rn(v);
    }
    #pragma unroll
    for (int o = 16; o; o >>= 1) s += __shfl_xor_sync(0xffffffffu, s, o);
    if ((t & 31) == 0) red[t >> 5] = s;
    __syncthreads();
    if (t == 0) g_cnorm[k] = (float)(red[0] + red[1] + red[2] + red[3]);
}

// ---------------------------------------------------------------------------
__global__ __launch_bounds__(NTHR, 1) void main_kernel(
    const float* __restrict__ E, const float* __restrict__ C, float* __restrict__ out)
{
    extern __shared__ __align__(1024) char smem[];
    const uint32_t sb = smem_u32(smem);
    const int tid  = threadIdx.x;
    const int wid  = tid >> 5;
    const int lane = tid & 31;
    const int row0 = blockIdx.x * BM;

    float* scoreS = (float*)(smem + OFF_SC);
    float* cnS    = (float*)(smem + OFF_CN);
    int*   idxS   = (int*)(smem + OFF_IDX);

    for (int i = tid; i < KC; i += NTHR) cnS[i] = g_cnorm[i];

    // ---- issue cp.async for B chunk 0 ----
    {
        const char* bsrc = (const char*)g_Bbf;   // chunk 0 = centroids 0..63
        #pragma unroll
        for (int j = 0; j < 16; j++) {
            int u = tid + NTHR * j;              // 4096 16B units: n = u>>6, c = u&63
            int n = u >> 6, c = u & 63;
            uint32_t dst = sb + OFF_B0 + n * 1024 + ((c ^ (n & 7)) << 4);
            cp16(dst, bsrc + n * 1024 + c * 16);
        }
        asm volatile("cp.async.commit_group;" ::: "memory");
    }

    // ---- fill A: load E fp32, convert bf16, swizzled STS ----
    #pragma unroll
    for (int j = 0; j < 32; j++) {
        int u = tid + NTHR * j;                  // 8192 float4 units: r = u>>7, q = u&127
        int r = u >> 7, q = u & 127;
        float4 f = *(const float4*)(E + (size_t)(row0 + r) * DIM + q * 4);
        uint2 v = make_uint2(b2u(__floats2bfloat162_rn(f.x, f.y)),
                             b2u(__floats2bfloat162_rn(f.z, f.w)));
        // k = q*4 ; chunk16 = q>>1 ; byte-within = (q&1)*8
        uint32_t off = r * 1024 + (((q >> 1) ^ (r & 7)) << 4) + ((q & 1) << 3);
        *(uint2*)(smem + OFF_A + off) = v;
    }

    // warp tile: rows [row0w, row0w+16), cols [col0w, col0w+32) within chunk
    const int row0w = (wid >> 1) * 16;
    const int col0w = (wid & 1) * 32;

    // ldmatrix lane geometry (precomputed)
    const int a_row  = row0w + (lane & 7) + ((lane >> 3) & 1) * 8;   // CTA row
    const int a_k8s  = (lane >> 4);                                   // k8 half
    const int b_nloc = col0w + ((lane >> 4) & 1) * 8 + (lane & 7);   // local col, + b*16
    const int b_k8s  = (lane >> 3) & 1;

    // per-row coarse top-8 (threads 0..63 own row tid)
    float tv[8]; int ti[8];
    #pragma unroll
    for (int q = 0; q < 8; q++) { tv[q] = 3.4e38f; ti[q] = 0x7fffffff; }

    for (int nc = 0; nc < NCHK; nc++) {
        // prefetch next B chunk into other buffer
        if (nc + 1 < NCHK) {
            const char* bsrc = (const char*)g_Bbf + (size_t)(nc + 1) * 64 * 1024;
            uint32_t bdst = sb + (((nc + 1) & 1) ? OFF_B1 : OFF_B0);
            #pragma unroll
            for (int j = 0; j < 16; j++) {
                int u = tid + NTHR * j;
                int n = u >> 6, c = u & 63;
                cp16(bdst + n * 1024 + ((c ^ (n & 7)) << 4), bsrc + n * 1024 + c * 16);
            }
            asm volatile("cp.async.commit_group;" ::: "memory");
            asm volatile("cp.async.wait_group 1;" ::: "memory");
        } else {
            asm volatile("cp.async.wait_group 0;" ::: "memory");
        }
        __syncthreads();

        const uint32_t aB = sb + OFF_A;
        const uint32_t bB = sb + ((nc & 1) ? OFF_B1 : OFF_B0);

        float d[4][4];
        #pragma unroll
        for (int nt = 0; nt < 4; nt++)
            #pragma unroll
            for (int e = 0; e < 4; e++) d[nt][e] = 0.0f;

        #pragma unroll 4
        for (int k16 = 0; k16 < 32; k16++) {
            uint32_t a[4];
            {
                int k8 = k16 * 2 + a_k8s;
                ldsm4(a[0], a[1], a[2], a[3],
                      aB + a_row * 1024 + ((k8 ^ (a_row & 7)) << 4));
            }
            uint32_t b[2][4];
            #pragma unroll
            for (int h = 0; h < 2; h++) {
                int n = b_nloc + h * 16;
                int k8 = k16 * 2 + b_k8s;
                ldsm4(b[h][0], b[h][1], b[h][2], b[h][3],
                      bB + n * 1024 + ((k8 ^ (n & 7)) << 4));
            }
            mma16816(d[0], a, &b[0][0]);
            mma16816(d[1], a, &b[0][2]);
            mma16816(d[2], a, &b[1][0]);
            mma16816(d[3], a, &b[1][2]);
        }

        // ---- stage dot products to smem (pitch 65) ----
        {
            int r = lane >> 2, cb = 2 * (lane & 3);
            #pragma unroll
            for (int nt = 0; nt < 4; nt++) {
                int col = col0w + nt * 8 + cb;
                scoreS[(row0w + r) * 65 + col]     = d[nt][0];
                scoreS[(row0w + r) * 65 + col + 1] = d[nt][1];
                scoreS[(row0w + r + 8) * 65 + col]     = d[nt][2];
                scoreS[(row0w + r + 8) * 65 + col + 1] = d[nt][3];
            }
        }
        __syncthreads();

        // ---- per-row top-8 update (threads 0..63) ----
        if (tid < BM) {
            #pragma unroll 8
            for (int c = 0; c < 64; c++) {
                int   gc  = nc * 64 + c;
                float val = cnS[gc] - 2.0f * scoreS[tid * 65 + c];
                if (ltp(val, gc, tv[7], ti[7])) {
                    tv[7] = val; ti[7] = gc;
                    #pragma unroll
                    for (int q = 7; q >= 1; q--)
                        if (ltp(tv[q], ti[q], tv[q - 1], ti[q - 1])) {
                            float fv = tv[q]; tv[q] = tv[q - 1]; tv[q - 1] = fv;
                            int   fi = ti[q]; ti[q] = ti[q - 1]; ti[q - 1] = fi;
                        }
                }
            }
        }
        __syncthreads();
    }

    // ---- exact rescore of candidates (threads 0..63, row = tid) ----
    if (tid < BM) {
        const float* erow = E + (size_t)(row0 + tid) * DIM;
        float b1 = 3.4e38f, b2v = 3.4e38f;
        int   i1 = 0x7fffffff, i2 = 0x7fffffff;
        const bool flagged = (tv[7] - tv[1] <= 6.0f);   // 2E margin
        const int  ncand = flagged ? KC : 8;
        for (int cc = 0; cc < ncand; cc++) {
            int k = flagged ? cc : ti[cc];
            const float* crow = C + (size_t)k * DIM;
            float acc = 0.0f;
            for (int c0 = 0; c0 < DIM; c0 += 16) {
                float p = 0.0f;
                #pragma unroll
                for (int g = 0; g < 4; g++) {
                    float4 ev = *(const float4*)(erow + c0 + g * 4);
                    float4 cv = *(const float4*)(crow + c0 + g * 4);
                    p = fmaf(ev.x, cv.x, p); p = fmaf(ev.y, cv.y, p);
                    p = fmaf(ev.z, cv.z, p); p = fmaf(ev.w, cv.w, p);
                }
                acc += p;
            }
            float s = cnS[k] - 2.0f * acc;
            if (ltp(s, k, b1, i1))        { b2v = b1; i2 = i1; b1 = s; i1 = k; }
            else if (ltp(s, k, b2v, i2))  { b2v = s; i2 = k; }
        }
        idxS[tid] = i2;
    }
    __syncthreads();

    // ---- gather output: out[row] = C[idx2[row]] ----
    #pragma unroll
    for (int j = 0; j < 32; j++) {
        int u = tid + NTHR * j;              // 8192 float4 units
        int r = u >> 7, q = u & 127;
        int src = idxS[r];
        *(float4*)(out + (size_t)(row0 + r) * DIM + q * 4) =
            *(const float4*)(C + (size_t)src * DIM + q * 4);
    }
}

extern "C" void kernel_launch(void* const* d_in, const int* in_sizes, int n_in,
                              void* d_out, int out_size) {
    const float* E = (const float*)d_in[0];
    const float* C = (const float*)d_in[1];
    float* out = (float*)d_out;
    (void)in_sizes; (void)n_in; (void)out_size;

    static int configured = 0;
    cudaFuncSetAttribute(main_kernel, cudaFuncAttributeMaxDynamicSharedMemorySize, SMEM_TOTAL);
    (void)configured;

    prep_kernel<<<KC, 128>>>(C);
    main_kernel<<<N_ROWS / BM, NTHR, SMEM_TOTAL>>>(E, C, out);
}

// round 6
// speedup vs baseline: 3.0751x; 3.0751x over previous
#include <cuda_runtime.h>
#include <cuda_bf16.h>
#include <cstdint>

#define N_ROWS 65536
#define DIM    512
#define KC     256
#define BM     64        // rows per CTA
#define NCHK   4         // 4 col-chunks of 64
#define NTHR   256
#define NCAND  8
#define TAU    6.0f

// smem byte offsets (dynamic smem)
#define OFF_A    0                 // 64 x 512 bf16 = 65536
#define OFF_B0   65536             // 64 x 512 bf16 = 65536
#define OFF_B1   131072
#define OFF_SC   196608            // 64 x 65 f32 = 16640
#define OFF_CN   213248            // 256 f32 = 1024
#define OFF_CAND 214272            // 64 x 8 int = 2048
#define OFF_IDX  216320            // 64 int
#define SMEM_TOTAL 216576

__device__ __nv_bfloat16 g_Bbf[KC][DIM];   // centroids, bf16, [k][d]
__device__ float g_cnorm[KC];
__device__ int   g_flag_cnt;
__device__ int   g_flag_rows[N_ROWS];

__device__ __forceinline__ uint32_t smem_u32(const void* p) {
    uint32_t a;
    asm("{ .reg .u64 t; cvta.to.shared.u64 t, %1; cvt.u32.u64 %0, t; }" : "=r"(a) : "l"(p));
    return a;
}
__device__ __forceinline__ void cp16(uint32_t s, const void* g) {
    asm volatile("cp.async.cg.shared.global [%0], [%1], 16;" :: "r"(s), "l"(g) : "memory");
}
__device__ __forceinline__ void ldsm4(uint32_t& r0, uint32_t& r1, uint32_t& r2, uint32_t& r3, uint32_t a) {
    asm volatile("ldmatrix.sync.aligned.m8n8.x4.shared.b16 {%0,%1,%2,%3}, [%4];"
                 : "=r"(r0), "=r"(r1), "=r"(r2), "=r"(r3) : "r"(a));
}
__device__ __forceinline__ void mma16816(float* d, const uint32_t* a, const uint32_t* b) {
    asm volatile("mma.sync.aligned.m16n8k16.row.col.f32.bf16.bf16.f32 "
                 "{%0,%1,%2,%3}, {%4,%5,%6,%7}, {%8,%9}, {%0,%1,%2,%3};"
                 : "+f"(d[0]), "+f"(d[1]), "+f"(d[2]), "+f"(d[3])
                 : "r"(a[0]), "r"(a[1]), "r"(a[2]), "r"(a[3]), "r"(b[0]), "r"(b[1]));
}
__device__ __forceinline__ uint32_t b2u(__nv_bfloat162 v) {
    return ((uint32_t)__bfloat16_as_ushort(v.y) << 16) | __bfloat16_as_ushort(v.x);
}
__device__ __forceinline__ bool ltp(float a, int ia, float b, int ib) {
    return a < b || (a == b && ia < ib);
}

// ---------------------------------------------------------------------------
__global__ void prep_kernel(const float* __restrict__ C) {
    __shared__ double red[4];
    const int k = blockIdx.x, t = threadIdx.x;   // 128 thr
    if (k == 0 && t == 0) g_flag_cnt = 0;        // deterministic across replays
    double s = 0.0;
    for (int d = t; d < DIM; d += 128) {
        float v = C[(size_t)k * DIM + d];
        s += (double)v * (double)v;
        g_Bbf[k][d] = __float2bfloat16_rn(v);
    }
    #pragma unroll
    for (int o = 16; o; o >>= 1) s += __shfl_xor_sync(0xffffffffu, s, o);
    if ((t & 31) == 0) red[t >> 5] = s;
    __syncthreads();
    if (t == 0) g_cnorm[k] = (float)(red[0] + red[1] + red[2] + red[3]);
}

// ---------------------------------------------------------------------------
__global__ __launch_bounds__(NTHR, 1) void main_kernel(
    const float* __restrict__ E, const float* __restrict__ C, float* __restrict__ out)
{
    extern __shared__ __align__(1024) char smem[];
    const uint32_t sb = smem_u32(smem);
    const int tid  = threadIdx.x;
    const int wid  = tid >> 5;
    const int lane = tid & 31;
    const int row0 = blockIdx.x * BM;

    float* scoreS = (float*)(smem + OFF_SC);
    float* cnS    = (float*)(smem + OFF_CN);
    int*   candS  = (int*)(smem + OFF_CAND);
    int*   idxS   = (int*)(smem + OFF_IDX);

    for (int i = tid; i < KC; i += NTHR) cnS[i] = g_cnorm[i];

    // ---- issue cp.async for B chunk 0 ----
    {
        const char* bsrc = (const char*)g_Bbf;
        #pragma unroll
        for (int j = 0; j < 16; j++) {
            int u = tid + NTHR * j;              // 4096 16B units
            int n = u >> 6, c = u & 63;
            cp16(sb + OFF_B0 + n * 1024 + ((c ^ (n & 7)) << 4), bsrc + n * 1024 + c * 16);
        }
        asm volatile("cp.async.commit_group;" ::: "memory");
    }

    // ---- fill A: load E fp32, convert bf16, swizzled STS ----
    #pragma unroll
    for (int j = 0; j < 32; j++) {
        int u = tid + NTHR * j;                  // 8192 float4 units
        int r = u >> 7, q = u & 127;
        float4 f = *(const float4*)(E + (size_t)(row0 + r) * DIM + q * 4);
        uint2 v = make_uint2(b2u(__floats2bfloat162_rn(f.x, f.y)),
                             b2u(__floats2bfloat162_rn(f.z, f.w)));
        uint32_t off = r * 1024 + (((q >> 1) ^ (r & 7)) << 4) + ((q & 1) << 3);
        *(uint2*)(smem + OFF_A + off) = v;
    }

    const int row0w = (wid >> 1) * 16;
    const int col0w = (wid & 1) * 32;
    const int a_row  = row0w + (lane & 7) + ((lane >> 3) & 1) * 8;
    const int a_k8s  = (lane >> 4);
    const int b_nloc = col0w + ((lane >> 4) & 1) * 8 + (lane & 7);
    const int b_k8s  = (lane >> 3) & 1;

    // per-row coarse top-8 (threads 0..63 own row tid)
    float tv[NCAND]; int ti[NCAND];
    #pragma unroll
    for (int q = 0; q < NCAND; q++) { tv[q] = 3.4e38f; ti[q] = 0x7fffffff; }

    for (int nc = 0; nc < NCHK; nc++) {
        if (nc + 1 < NCHK) {
            const char* bsrc = (const char*)g_Bbf + (size_t)(nc + 1) * 64 * 1024;
            uint32_t bdst = sb + (((nc + 1) & 1) ? OFF_B1 : OFF_B0);
            #pragma unroll
            for (int j = 0; j < 16; j++) {
                int u = tid + NTHR * j;
                int n = u >> 6, c = u & 63;
                cp16(bdst + n * 1024 + ((c ^ (n & 7)) << 4), bsrc + n * 1024 + c * 16);
            }
            asm volatile("cp.async.commit_group;" ::: "memory");
            asm volatile("cp.async.wait_group 1;" ::: "memory");
        } else {
            asm volatile("cp.async.wait_group 0;" ::: "memory");
        }
        __syncthreads();

        const uint32_t aB = sb + OFF_A;
        const uint32_t bB = sb + ((nc & 1) ? OFF_B1 : OFF_B0);

        float d[4][4];
        #pragma unroll
        for (int nt = 0; nt < 4; nt++)
            #pragma unroll
            for (int e = 0; e < 4; e++) d[nt][e] = 0.0f;

        #pragma unroll 4
        for (int k16 = 0; k16 < 32; k16++) {
            uint32_t a[4];
            {
                int k8 = k16 * 2 + a_k8s;
                ldsm4(a[0], a[1], a[2], a[3],
                      aB + a_row * 1024 + ((k8 ^ (a_row & 7)) << 4));
            }
            uint32_t b[2][4];
            #pragma unroll
            for (int h = 0; h < 2; h++) {
                int n = b_nloc + h * 16;
                int k8 = k16 * 2 + b_k8s;
                ldsm4(b[h][0], b[h][1], b[h][2], b[h][3],
                      bB + n * 1024 + ((k8 ^ (n & 7)) << 4));
            }
            mma16816(d[0], a, &b[0][0]);
            mma16816(d[1], a, &b[0][2]);
            mma16816(d[2], a, &b[1][0]);
            mma16816(d[3], a, &b[1][2]);
        }

        // stage dot products to smem (pitch 65)
        {
            int r = lane >> 2, cb = 2 * (lane & 3);
            #pragma unroll
            for (int nt = 0; nt < 4; nt++) {
                int col = col0w + nt * 8 + cb;
                scoreS[(row0w + r) * 65 + col]     = d[nt][0];
                scoreS[(row0w + r) * 65 + col + 1] = d[nt][1];
                scoreS[(row0w + r + 8) * 65 + col]     = d[nt][2];
                scoreS[(row0w + r + 8) * 65 + col + 1] = d[nt][3];
            }
        }
        __syncthreads();

        // per-row coarse top-8 update (threads 0..63)
        if (tid < BM) {
            #pragma unroll 8
            for (int c = 0; c < 64; c++) {
                int   gc  = nc * 64 + c;
                float val = cnS[gc] - 2.0f * scoreS[tid * 65 + c];
                if (ltp(val, gc, tv[NCAND - 1], ti[NCAND - 1])) {
                    tv[NCAND - 1] = val; ti[NCAND - 1] = gc;
                    #pragma unroll
                    for (int q = NCAND - 1; q >= 1; q--)
                        if (ltp(tv[q], ti[q], tv[q - 1], ti[q - 1])) {
                            float fv = tv[q]; tv[q] = tv[q - 1]; tv[q - 1] = fv;
                            int   fi = ti[q]; ti[q] = ti[q - 1]; ti[q - 1] = fi;
                        }
                }
            }
        }
        __syncthreads();
    }

    // ---- publish candidates + flag ambiguous rows (containment margin) ----
    if (tid < BM) {
        #pragma unroll
        for (int q = 0; q < NCAND; q++) candS[tid * NCAND + q] = ti[q];
        if (tv[NCAND - 1] - tv[1] <= TAU) {
            int p = atomicAdd(&g_flag_cnt, 1);
            g_flag_rows[p] = row0 + tid;
        }
    }
    __syncthreads();

    // ---- PARALLEL exact rescore: warp w owns rows [8w, 8w+8) ----
    for (int i = 0; i < 8; i++) {
        const int row = wid * 8 + i;
        const float4* e4 = (const float4*)(E + (size_t)(row0 + row) * DIM);
        float4 ef[4];
        #pragma unroll
        for (int q = 0; q < 4; q++) ef[q] = e4[lane + 32 * q];   // coalesced, L1-hot
        int cd[NCAND];
        #pragma unroll
        for (int c = 0; c < NCAND; c++) cd[c] = candS[row * NCAND + c];
        float acc[NCAND];
        #pragma unroll
        for (int c = 0; c < NCAND; c++) {
            const float4* c4 = (const float4*)(C + (size_t)cd[c] * DIM);
            float p = 0.0f;
            #pragma unroll
            for (int q = 0; q < 4; q++) {
                float4 cv = c4[lane + 32 * q];
                p = fmaf(ef[q].x, cv.x, p); p = fmaf(ef[q].y, cv.y, p);
                p = fmaf(ef[q].z, cv.z, p); p = fmaf(ef[q].w, cv.w, p);
            }
            acc[c] = p;
        }
        #pragma unroll
        for (int off = 16; off; off >>= 1)
            #pragma unroll
            for (int c = 0; c < NCAND; c++)
                acc[c] += __shfl_xor_sync(0xffffffffu, acc[c], off);
        if (lane == 0) {
            float b1 = 3.4e38f, b2v = 3.4e38f;
            int   i1 = 0x7fffffff, i2 = 0x7fffffff;
            #pragma unroll
            for (int c = 0; c < NCAND; c++) {
                float s = cnS[cd[c]] - 2.0f * acc[c];
                if (ltp(s, cd[c], b1, i1))       { b2v = b1; i2 = i1; b1 = s; i1 = cd[c]; }
                else if (ltp(s, cd[c], b2v, i2)) { b2v = s; i2 = cd[c]; }
            }
            idxS[row] = i2;
        }
    }
    __syncthreads();

    // ---- gather output: out[row] = C[idx2[row]] ----
    #pragma unroll
    for (int j = 0; j < 32; j++) {
        int u = tid + NTHR * j;              // 8192 float4 units
        int r = u >> 7, q = u & 127;
        int src = idxS[r];
        *(float4*)(out + (size_t)(row0 + r) * DIM + q * 4) =
            *(const float4*)(C + (size_t)src * DIM + q * 4);
    }
}

// ---------------------------------------------------------------------------
// Cleanup: exact fp32 full rescan of margin-flagged rows, one centroid per
// thread (fully parallel; no serial-chain tail).
// ---------------------------------------------------------------------------
__global__ void cleanup_kernel(const float* __restrict__ E, const float* __restrict__ C,
                               float* __restrict__ out)
{
    __shared__ float es[DIM];
    __shared__ float sc[KC];
    __shared__ int   bi2;
    const int t = threadIdx.x;    // 256
    const int nflag = g_flag_cnt;
    for (int i = blockIdx.x; i < nflag; i += gridDim.x) {
        int row = g_flag_rows[i];
        __syncthreads();
        for (int d = t; d < DIM; d += 256) es[d] = E[(size_t)row * DIM + d];
        __syncthreads();
        const float* cr = C + (size_t)t * DIM;
        float acc = 0.0f;
        for (int c0 = 0; c0 < DIM; c0 += 16) {
            float p = 0.0f;
            #pragma unroll
            for (int dd = 0; dd < 16; dd++) p = fmaf(es[c0 + dd], cr[c0 + dd], p);
            acc += p;
        }
        sc[t] = g_cnorm[t] - 2.0f * acc;
        __syncthreads();
        if (t == 0) {
            float v1 = 3.4e38f, v2 = 3.4e38f; int j1 = -1, j2 = -1;
            for (int k = 0; k < KC; k++) {
                float s = sc[k];
                if (ltp(s, k, v1, j1))      { v2 = v1; j2 = j1; v1 = s; j1 = k; }
                else if (ltp(s, k, v2, j2)) { v2 = s; j2 = k; }
            }
            bi2 = j2;
        }
        __syncthreads();
        int src = bi2;
        for (int d = t; d < DIM; d += 256) out[(size_t)row * DIM + d] = C[(size_t)src * DIM + d];
    }
}

extern "C" void kernel_launch(void* const* d_in, const int* in_sizes, int n_in,
                              void* d_out, int out_size) {
    const float* E = (const float*)d_in[0];
    const float* C = (const float*)d_in[1];
    float* out = (float*)d_out;
    (void)in_sizes; (void)n_in; (void)out_size;

    cudaFuncSetAttribute(main_kernel, cudaFuncAttributeMaxDynamicSharedMemorySize, SMEM_TOTAL);
    prep_kernel<<<KC, 128>>>(C);
    main_kernel<<<N_ROWS / BM, NTHR, SMEM_TOTAL>>>(E, C, out);
    cleanup_kernel<<<256, 256>>>(E, C, out);
}

// round 7
// speedup vs baseline: 4.2914x; 1.3955x over previous
#include <cuda_runtime.h>
#include <cuda_bf16.h>
#include <cstdint>

#define N_ROWS 65536
#define DIM    512
#define KC     256
#define BM     32        // rows per CTA
#define CCH    32        // centroids per chunk
#define NCHK   8
#define NTHR   128
#define NCAND  8
#define TAU    6.0f

// smem byte offsets (dynamic)
#define OFF_A    0                 // 32 x 512 bf16 = 32768
#define OFF_B0   32768             // 32 x 512 bf16 = 32768
#define OFF_B1   65536
#define OFF_SC   98304             // 32 x 33 f32 = 4224
#define OFF_CN   102528            // 256 f32
#define OFF_CAND 103552            // 32 x 8 int
#define SMEM_TOTAL 104576          // ~102KB -> 2 CTAs/SM

__device__ __nv_bfloat16 g_Bbf[KC][DIM];
__device__ float g_cnorm[KC];
__device__ int   g_idx[N_ROWS];
__device__ int   g_flag_cnt;
__device__ int   g_flag_rows[N_ROWS];

__device__ __forceinline__ uint32_t smem_u32(const void* p) {
    uint32_t a;
    asm("{ .reg .u64 t; cvta.to.shared.u64 t, %1; cvt.u32.u64 %0, t; }" : "=r"(a) : "l"(p));
    return a;
}
__device__ __forceinline__ void cp16(uint32_t s, const void* g) {
    asm volatile("cp.async.cg.shared.global [%0], [%1], 16;" :: "r"(s), "l"(g) : "memory");
}
__device__ __forceinline__ void ldsm4(uint32_t& r0, uint32_t& r1, uint32_t& r2, uint32_t& r3, uint32_t a) {
    asm volatile("ldmatrix.sync.aligned.m8n8.x4.shared.b16 {%0,%1,%2,%3}, [%4];"
                 : "=r"(r0), "=r"(r1), "=r"(r2), "=r"(r3) : "r"(a));
}
__device__ __forceinline__ void mma16816(float* d, const uint32_t* a, const uint32_t* b) {
    asm volatile("mma.sync.aligned.m16n8k16.row.col.f32.bf16.bf16.f32 "
                 "{%0,%1,%2,%3}, {%4,%5,%6,%7}, {%8,%9}, {%0,%1,%2,%3};"
                 : "+f"(d[0]), "+f"(d[1]), "+f"(d[2]), "+f"(d[3])
                 : "r"(a[0]), "r"(a[1]), "r"(a[2]), "r"(a[3]), "r"(b[0]), "r"(b[1]));
}
__device__ __forceinline__ uint32_t b2u(__nv_bfloat162 v) {
    return ((uint32_t)__bfloat16_as_ushort(v.y) << 16) | __bfloat16_as_ushort(v.x);
}
__device__ __forceinline__ bool ltp(float a, int ia, float b, int ib) {
    return a < b || (a == b && ia < ib);
}

// ---------------------------------------------------------------------------
__global__ void prep_kernel(const float* __restrict__ C) {
    __shared__ double red[4];
    const int k = blockIdx.x, t = threadIdx.x;   // 128 thr
    if (k == 0 && t == 0) g_flag_cnt = 0;
    double s = 0.0;
    for (int d = t; d < DIM; d += 128) {
        float v = C[(size_t)k * DIM + d];
        s += (double)v * (double)v;
        g_Bbf[k][d] = __float2bfloat16_rn(v);
    }
    #pragma unroll
    for (int o = 16; o; o >>= 1) s += __shfl_xor_sync(0xffffffffu, s, o);
    if ((t & 31) == 0) red[t >> 5] = s;
    __syncthreads();
    if (t == 0) g_cnorm[k] = (float)(red[0] + red[1] + red[2] + red[3]);
}

// ---------------------------------------------------------------------------
// Score kernel: 32 rows x 256 cents per CTA, HMMA coarse + exact rescore.
// ---------------------------------------------------------------------------
__global__ __launch_bounds__(NTHR, 2) void score_kernel(
    const float* __restrict__ E, const float* __restrict__ C)
{
    extern __shared__ __align__(1024) char smem[];
    const uint32_t sb = smem_u32(smem);
    const int tid  = threadIdx.x;
    const int wid  = tid >> 5;      // 0..3
    const int lane = tid & 31;
    const int row0 = blockIdx.x * BM;

    float* scoreS = (float*)(smem + OFF_SC);
    float* cnS    = (float*)(smem + OFF_CN);
    int*   candS  = (int*)(smem + OFF_CAND);

    for (int i = tid; i < KC; i += NTHR) cnS[i] = g_cnorm[i];

    // ---- prefetch B chunk 0 (32 cents x 512d bf16 = 32KB) ----
    {
        const char* bsrc = (const char*)g_Bbf;
        #pragma unroll
        for (int j = 0; j < 16; j++) {
            int u = tid + NTHR * j;              // 2048 16B units: n = u>>6, c = u&63
            int n = u >> 6, c = u & 63;
            cp16(sb + OFF_B0 + n * 1024 + ((c ^ (n & 7)) << 4), bsrc + n * 1024 + c * 16);
        }
        asm volatile("cp.async.commit_group;" ::: "memory");
    }

    // ---- fill A: 32 rows of E, f32 -> bf16, swizzled ----
    #pragma unroll
    for (int j = 0; j < 32; j++) {
        int u = tid + NTHR * j;                  // 4096 float4 units
        int r = u >> 7, q = u & 127;
        float4 f = *(const float4*)(E + (size_t)(row0 + r) * DIM + q * 4);
        uint2 v = make_uint2(b2u(__floats2bfloat162_rn(f.x, f.y)),
                             b2u(__floats2bfloat162_rn(f.z, f.w)));
        uint32_t off = r * 1024 + (((q >> 1) ^ (r & 7)) << 4) + ((q & 1) << 3);
        *(uint2*)(smem + OFF_A + off) = v;
    }

    // warp tile: rows (wid&1)*16.. +16, cents (wid>>1)*16.. +16 within chunk
    const int row0w = (wid & 1) * 16;
    const int c0w   = (wid >> 1) * 16;
    const int a_row  = row0w + (lane & 7) + ((lane >> 3) & 1) * 8;
    const int a_k8s  = (lane >> 4);
    const int b_nloc = c0w + ((lane >> 4) & 1) * 8 + (lane & 7);
    const int b_k8s  = (lane >> 3) & 1;

    // per-thread local top-8 over its 64 disjoint cents (row = tid>>2, part = tid&3)
    const int selrow  = tid >> 2;
    const int selpart = tid & 3;
    float tv[NCAND]; int ti[NCAND];
    #pragma unroll
    for (int q = 0; q < NCAND; q++) { tv[q] = 3.4e38f; ti[q] = 0x7fffffff; }

    for (int nc = 0; nc < NCHK; nc++) {
        if (nc + 1 < NCHK) {
            const char* bsrc = (const char*)g_Bbf + (size_t)(nc + 1) * CCH * 1024;
            uint32_t bdst = sb + (((nc + 1) & 1) ? OFF_B1 : OFF_B0);
            #pragma unroll
            for (int j = 0; j < 16; j++) {
                int u = tid + NTHR * j;
                int n = u >> 6, c = u & 63;
                cp16(bdst + n * 1024 + ((c ^ (n & 7)) << 4), bsrc + n * 1024 + c * 16);
            }
            asm volatile("cp.async.commit_group;" ::: "memory");
            asm volatile("cp.async.wait_group 1;" ::: "memory");
        } else {
            asm volatile("cp.async.wait_group 0;" ::: "memory");
        }
        __syncthreads();

        const uint32_t aB = sb + OFF_A;
        const uint32_t bB = sb + ((nc & 1) ? OFF_B1 : OFF_B0);

        float d[2][4];
        #pragma unroll
        for (int nt = 0; nt < 2; nt++)
            #pragma unroll
            for (int e = 0; e < 4; e++) d[nt][e] = 0.0f;

        #pragma unroll 4
        for (int k16 = 0; k16 < 32; k16++) {
            uint32_t a[4];
            {
                int k8 = k16 * 2 + a_k8s;
                ldsm4(a[0], a[1], a[2], a[3],
                      aB + a_row * 1024 + ((k8 ^ (a_row & 7)) << 4));
            }
            uint32_t b[4];
            {
                int k8 = k16 * 2 + b_k8s;
                ldsm4(b[0], b[1], b[2], b[3],
                      bB + b_nloc * 1024 + ((k8 ^ (b_nloc & 7)) << 4));
            }
            mma16816(d[0], a, &b[0]);
            mma16816(d[1], a, &b[2]);
        }

        // stage dot products to smem (pitch 33)
        {
            int r = lane >> 2, cb = 2 * (lane & 3);
            #pragma unroll
            for (int nt = 0; nt < 2; nt++) {
                int col = c0w + nt * 8 + cb;
                scoreS[(row0w + r) * 33 + col]     = d[nt][0];
                scoreS[(row0w + r) * 33 + col + 1] = d[nt][1];
                scoreS[(row0w + r + 8) * 33 + col]     = d[nt][2];
                scoreS[(row0w + r + 8) * 33 + col + 1] = d[nt][3];
            }
        }
        __syncthreads();

        // all 128 threads: local top-8 update over this chunk's 8 cents
        #pragma unroll
        for (int j = 0; j < 8; j++) {
            int   cc  = selpart * 8 + j;
            int   gc  = nc * CCH + cc;
            float val = cnS[gc] - 2.0f * scoreS[selrow * 33 + cc];
            if (ltp(val, gc, tv[NCAND - 1], ti[NCAND - 1])) {
                tv[NCAND - 1] = val; ti[NCAND - 1] = gc;
                #pragma unroll
                for (int q = NCAND - 1; q >= 1; q--)
                    if (ltp(tv[q], ti[q], tv[q - 1], ti[q - 1])) {
                        float fv = tv[q]; tv[q] = tv[q - 1]; tv[q - 1] = fv;
                        int   fi = ti[q]; ti[q] = ti[q - 1]; ti[q - 1] = fi;
                    }
            }
        }
        __syncthreads();
    }

    // ---- merge 4 partial top-8s per row (exact: subsets are disjoint) ----
    // merge buffer aliases dead B0 (last compute used B1)
    float* mvS = (float*)(smem + OFF_B0);            // 32*32 floats
    int*   miS = (int*)(smem + OFF_B0 + 4096);       // 32*32 ints
    #pragma unroll
    for (int q = 0; q < NCAND; q++) {
        mvS[(selrow * 4 + selpart) * 8 + q] = tv[q];
        miS[(selrow * 4 + selpart) * 8 + q] = ti[q];
    }
    __syncthreads();
    if (tid < BM) {
        float rv[NCAND]; int ri[NCAND];
        #pragma unroll
        for (int q = 0; q < NCAND; q++) { rv[q] = 3.4e38f; ri[q] = 0x7fffffff; }
        for (int e = 0; e < 32; e++) {
            float v = mvS[tid * 32 + e]; int ix = miS[tid * 32 + e];
            if (ltp(v, ix, rv[NCAND - 1], ri[NCAND - 1])) {
                rv[NCAND - 1] = v; ri[NCAND - 1] = ix;
                #pragma unroll
                for (int q = NCAND - 1; q >= 1; q--)
                    if (ltp(rv[q], ri[q], rv[q - 1], ri[q - 1])) {
                        float fv = rv[q]; rv[q] = rv[q - 1]; rv[q - 1] = fv;
                        int   fi = ri[q]; ri[q] = ri[q - 1]; ri[q - 1] = fi;
                    }
            }
        }
        #pragma unroll
        for (int q = 0; q < NCAND; q++) candS[tid * NCAND + q] = ri[q];
        if (rv[NCAND - 1] - rv[1] <= TAU) {           // containment margin
            int p = atomicAdd(&g_flag_cnt, 1);
            g_flag_rows[p] = row0 + tid;
        }
    }
    __syncthreads();

    // ---- exact fp32 rescore of 8 candidates: warp w owns rows 8w..8w+8 ----
    for (int i = 0; i < 8; i++) {
        const int row = wid * 8 + i;
        const float4* e4 = (const float4*)(E + (size_t)(row0 + row) * DIM);
        float4 ef[4];
        #pragma unroll
        for (int q = 0; q < 4; q++) ef[q] = e4[lane + 32 * q];   // L1-hot
        int cd[NCAND];
        #pragma unroll
        for (int c = 0; c < NCAND; c++) cd[c] = candS[row * NCAND + c];
        float acc[NCAND];
        #pragma unroll
        for (int c = 0; c < NCAND; c++) {
            const float4* c4 = (const float4*)(C + (size_t)cd[c] * DIM);
            float p = 0.0f;
            #pragma unroll
            for (int q = 0; q < 4; q++) {
                float4 cv = c4[lane + 32 * q];
                p = fmaf(ef[q].x, cv.x, p); p = fmaf(ef[q].y, cv.y, p);
                p = fmaf(ef[q].z, cv.z, p); p = fmaf(ef[q].w, cv.w, p);
            }
            acc[c] = p;
        }
        #pragma unroll
        for (int off = 16; off; off >>= 1)
            #pragma unroll
            for (int c = 0; c < NCAND; c++)
                acc[c] += __shfl_xor_sync(0xffffffffu, acc[c], off);
        if (lane == 0) {
            float b1 = 3.4e38f, b2v = 3.4e38f;
            int   i1 = 0x7fffffff, i2 = 0x7fffffff;
            #pragma unroll
            for (int c = 0; c < NCAND; c++) {
                float s = cnS[cd[c]] - 2.0f * acc[c];
                if (ltp(s, cd[c], b1, i1))       { b2v = b1; i2 = i1; b1 = s; i1 = cd[c]; }
                else if (ltp(s, cd[c], b2v, i2)) { b2v = s; i2 = cd[c]; }
            }
            g_idx[row0 + row] = i2;
        }
    }
}

// ---------------------------------------------------------------------------
// Cleanup: exact full 256-cent rescan of flagged rows -> fixes g_idx.
// ---------------------------------------------------------------------------
__global__ void cleanup_kernel(const float* __restrict__ E, const float* __restrict__ C)
{
    __shared__ float es[DIM];
    __shared__ float sc[KC];
    const int t = threadIdx.x;    // 256
    const int nflag = g_flag_cnt;
    for (int i = blockIdx.x; i < nflag; i += gridDim.x) {
        int row = g_flag_rows[i];
        __syncthreads();
        for (int d = t; d < DIM; d += 256) es[d] = E[(size_t)row * DIM + d];
        __syncthreads();
        const float* cr = C + (size_t)t * DIM;
        float acc = 0.0f;
        for (int c0 = 0; c0 < DIM; c0 += 16) {
            float p = 0.0f;
            #pragma unroll
            for (int dd = 0; dd < 16; dd++) p = fmaf(es[c0 + dd], cr[c0 + dd], p);
            acc += p;
        }
        sc[t] = g_cnorm[t] - 2.0f * acc;
        __syncthreads();
        if (t == 0) {
            float v1 = 3.4e38f, v2 = 3.4e38f; int j1 = -1, j2 = -1;
            for (int k = 0; k < KC; k++) {
                float s = sc[k];
                if (ltp(s, k, v1, j1))      { v2 = v1; j2 = j1; v1 = s; j1 = k; }
                else if (ltp(s, k, v2, j2)) { v2 = s; j2 = k; }
            }
            g_idx[row] = j2;
        }
        __syncthreads();
    }
}

// ---------------------------------------------------------------------------
// Gather: out[row] = C[g_idx[row]]  — pure bandwidth.
// ---------------------------------------------------------------------------
__global__ __launch_bounds__(256) void gather_kernel(const float* __restrict__ C,
                                                     float* __restrict__ out)
{
    __shared__ int idxS[32];
    const int t = threadIdx.x;
    const int row0 = blockIdx.x * 32;
    if (t < 32) idxS[t] = g_idx[row0 + t];
    __syncthreads();
    #pragma unroll
    for (int j = 0; j < 16; j++) {
        int u = t + 256 * j;                 // 4096 float4 units
        int r = u >> 7, q = u & 127;
        *(float4*)(out + (size_t)(row0 + r) * DIM + q * 4) =
            *(const float4*)(C + (size_t)idxS[r] * DIM + q * 4);
    }
}

extern "C" void kernel_launch(void* const* d_in, const int* in_sizes, int n_in,
                              void* d_out, int out_size) {
    const float* E = (const float*)d_in[0];
    const float* C = (const float*)d_in[1];
    float* out = (float*)d_out;
    (void)in_sizes; (void)n_in; (void)out_size;

    cudaFuncSetAttribute(score_kernel, cudaFuncAttributeMaxDynamicSharedMemorySize, SMEM_TOTAL);
    prep_kernel<<<KC, 128>>>(C);
    score_kernel<<<N_ROWS / BM, NTHR, SMEM_TOTAL>>>(E, C);
    cleanup_kernel<<<256, 256>>>(E, C);
    gather_kernel<<<N_ROWS / 32, 256>>>(C, out);
}